// round 2
// baseline (speedup 1.0000x reference)
#include <cuda_runtime.h>
#include <cstdint>

// Problem constants (match reference)
#define N_SOLID     2000
#define OMEGA_C     6283.185307179586f      // 2*pi*1000
#define PENALTY_C   1.0e8f
#define C_F_C       343.0f
#define P0_C        1.0f

// ---------------------------------------------------------------------------
// Helper: tet gradients + volume from 4 vertex coords
// g[i][d] = d N_i / d x_d ;  V = |det|/6
// ---------------------------------------------------------------------------
__device__ __forceinline__ void tet_grads(const float x[4][3], float g[4][3], float& V)
{
    float v1[3], v2[3], v3[3];
#pragma unroll
    for (int d = 0; d < 3; d++) {
        v1[d] = x[1][d] - x[0][d];
        v2[d] = x[2][d] - x[0][d];
        v3[d] = x[3][d] - x[0][d];
    }
    float c23[3] = { v2[1]*v3[2] - v2[2]*v3[1],
                     v2[2]*v3[0] - v2[0]*v3[2],
                     v2[0]*v3[1] - v2[1]*v3[0] };
    float c31[3] = { v3[1]*v1[2] - v3[2]*v1[1],
                     v3[2]*v1[0] - v3[0]*v1[2],
                     v3[0]*v1[1] - v3[1]*v1[0] };
    float c12[3] = { v1[1]*v2[2] - v1[2]*v2[1],
                     v1[2]*v2[0] - v1[0]*v2[2],
                     v1[0]*v2[1] - v1[1]*v2[0] };
    float det = v1[0]*c23[0] + v1[1]*c23[1] + v1[2]*c23[2];
    float inv = 1.0f / det;
#pragma unroll
    for (int d = 0; d < 3; d++) {
        g[1][d] = c23[d] * inv;
        g[2][d] = c31[d] * inv;
        g[3][d] = c12[d] * inv;
        g[0][d] = -(g[1][d] + g[2][d] + g[3][d]);
    }
    V = fabsf(det) * (1.0f / 6.0f);
}

// ---------------------------------------------------------------------------
// K1: fluid assembly  A[id_i, id_j] += Ke - k^2 * Me   (atomic)
// ---------------------------------------------------------------------------
__global__ void k_fluid_assemble(const float* __restrict__ nodes,
                                 const int*   __restrict__ elems,
                                 float* __restrict__ A,
                                 int Ef, int nt, float k2)
{
    int e = blockIdx.x * blockDim.x + threadIdx.x;
    if (e >= Ef) return;

    int id[4];
    float x[4][3];
#pragma unroll
    for (int i = 0; i < 4; i++) {
        id[i] = elems[e * 4 + i];
#pragma unroll
        for (int d = 0; d < 3; d++) x[i][d] = nodes[id[i] * 3 + d];
    }
    float g[4][3], V;
    tet_grads(x, g, V);
    float mscale = k2 * V * 0.1f;

#pragma unroll
    for (int i = 0; i < 4; i++) {
#pragma unroll
        for (int j = 0; j < 4; j++) {
            float ke = V * (g[i][0]*g[j][0] + g[i][1]*g[j][1] + g[i][2]*g[j][2]);
            float me = mscale * ((i == j) ? 3.0f : 1.0f);
            atomicAdd(&A[(size_t)id[i] * nt + id[j]], ke - me);
        }
    }
}

// ---------------------------------------------------------------------------
// K2: Dirichlet rows — zero row over fluid columns, diag = 1, F[row] = p0.
// Grid: (blocksPerRow, Nn). Solid columns [n,nt) stay zero from memset.
// ---------------------------------------------------------------------------
__global__ void k_dirichlet(const int* __restrict__ near_idx,
                            float* __restrict__ A,
                            float* __restrict__ F,
                            int n, int nt)
{
    int row = near_idx[blockIdx.y];
    float* Arow = A + (size_t)row * nt;
    int stride = blockDim.x * gridDim.x;
    for (int c = blockIdx.x * blockDim.x + threadIdx.x; c < n; c += stride)
        Arow[c] = (c == row) ? 1.0f : 0.0f;
    if (threadIdx.x == 0 && blockIdx.x == 0) F[row] = P0_C;
}

// ---------------------------------------------------------------------------
// K3: fluid interface penalty — diag += PENALTY (duplicates accumulate)
// ---------------------------------------------------------------------------
__global__ void k_fluid_penalty(const int* __restrict__ imap,
                                float* __restrict__ A,
                                int Ni, int nt)
{
    int t = blockIdx.x * blockDim.x + threadIdx.x;
    if (t >= Ni) return;
    int m = imap[t];
    atomicAdd(&A[(size_t)m * nt + m], PENALTY_C);
}

// ---------------------------------------------------------------------------
// K4: solid assembly. One thread per (element, node-pair a,b); writes the 3x3
// block via closed-form isotropic B^T D B:
//   K[i][j] = V*( lam*ga_i*gb_j + mu*ga_j*gb_i + mu*delta_ij*(ga.gb) )
// minus lumped mass w2*rho*V/4 on the diagonal.
// ---------------------------------------------------------------------------
__global__ void k_solid_assemble(const float* __restrict__ nodes,
                                 const int*   __restrict__ elems,
                                 const float* __restrict__ pE,
                                 const float* __restrict__ pNu,
                                 const float* __restrict__ pRho,
                                 float* __restrict__ A,
                                 int Es, int n, int nt)
{
    int t = blockIdx.x * blockDim.x + threadIdx.x;
    int e = t >> 4;
    if (e >= Es) return;
    int pr = t & 15;
    int a = pr >> 2, b = pr & 3;

    float E   = pE[0];
    float nu  = pNu[0];
    float rho = pRho[0];
    float coeff = E / ((1.0f + nu) * (1.0f - 2.0f * nu));
    float lam = coeff * nu;
    float mu  = coeff * 0.5f * (1.0f - 2.0f * nu);
    float w2  = OMEGA_C * OMEGA_C;

    int loc[4];
    float x[4][3];
    int base = n - N_SOLID;
#pragma unroll
    for (int i = 0; i < 4; i++) {
        loc[i] = elems[e * 4 + i];
#pragma unroll
        for (int d = 0; d < 3; d++) x[i][d] = nodes[(base + loc[i]) * 3 + d];
    }
    float g[4][3], V;
    tet_grads(x, g, V);

    float ga[3] = { g[a][0], g[a][1], g[a][2] };
    float gb[3] = { g[b][0], g[b][1], g[b][2] };
    float dot = ga[0]*gb[0] + ga[1]*gb[1] + ga[2]*gb[2];
    float mass = (a == b) ? (w2 * rho * V * 0.25f) : 0.0f;

    size_t rbase = (size_t)(n + loc[a] * 3) * nt + (n + loc[b] * 3);

#pragma unroll
    for (int i = 0; i < 3; i++) {
#pragma unroll
        for (int j = 0; j < 3; j++) {
            float val = V * (lam * ga[i] * gb[j] + mu * ga[j] * gb[i]);
            if (i == j) val += V * mu * dot - mass;
            atomicAdd(&A[rbase + (size_t)i * nt + j], val);
        }
    }
}

// ---------------------------------------------------------------------------
// K5: solid interface penalty — pm = PENALTY * outer(n0, n0), n0 = normals[0]
// ---------------------------------------------------------------------------
__global__ void k_solid_penalty(const int*   __restrict__ isol,
                                const float* __restrict__ normals,
                                float* __restrict__ A,
                                int Ni, int n, int nt)
{
    int t = blockIdx.x * blockDim.x + threadIdx.x;
    if (t >= Ni * 9) return;
    int s  = t / 9;
    int ij = t - s * 9;
    int i  = ij / 3, j = ij - i * 3;
    float n0i = normals[i];
    float n0j = normals[j];
    int sl = isol[s];
    size_t row = (size_t)(n + sl * 3 + i);
    size_t col = (size_t)(n + sl * 3 + j);
    atomicAdd(&A[row * nt + col], PENALTY_C * n0i * n0j);
}

// ---------------------------------------------------------------------------
extern "C" void kernel_launch(void* const* d_in, const int* in_sizes, int n_in,
                              void* d_out, int out_size)
{
    const float* nodes   = (const float*)d_in[0];
    const int*   f_elems = (const int*)  d_in[1];
    const int*   s_elems = (const int*)  d_in[2];
    const int*   imap    = (const int*)  d_in[3];
    const int*   isol    = (const int*)  d_in[4];
    const float* normals = (const float*)d_in[5];
    const int*   near_i  = (const int*)  d_in[6];
    const float* pE      = (const float*)d_in[7];
    const float* pNu     = (const float*)d_in[8];
    const float* pRho    = (const float*)d_in[9];

    int n  = in_sizes[0] / 3;          // 8000
    int Ef = in_sizes[1] / 4;          // 40000
    int Es = in_sizes[2] / 4;          // 10000
    int Ni = in_sizes[3];              // 400
    int Nn = in_sizes[6];              // 200
    int nt = n + 3 * N_SOLID;          // 14000

    float* A = (float*)d_out;
    float* F = A + (size_t)nt * nt;

    float kwav = OMEGA_C / C_F_C;
    float k2   = kwav * kwav;

    // Zero-fill A_g and F_g (dominant cost: ~784 MB streaming store)
    cudaMemsetAsync(d_out, 0, (size_t)out_size * sizeof(float), 0);

    // Fluid assembly (atomic scatter)
    {
        int threads = 256;
        int blocks  = (Ef + threads - 1) / threads;
        k_fluid_assemble<<<blocks, threads>>>(nodes, f_elems, A, Ef, nt, k2);
    }

    // Solid assembly — disjoint [n,nt) block; order vs fluid irrelevant
    {
        int total   = Es * 16;
        int threads = 256;
        int blocks  = (total + threads - 1) / threads;
        k_solid_assemble<<<blocks, threads>>>(nodes, s_elems, pE, pNu, pRho,
                                              A, Es, n, nt);
    }

    // Solid interface penalty
    {
        int total   = Ni * 9;
        int threads = 128;
        int blocks  = (total + threads - 1) / threads;
        k_solid_penalty<<<blocks, threads>>>(isol, normals, A, Ni, n, nt);
    }

    // Dirichlet BCs (must follow fluid assembly)
    {
        dim3 grid(4, Nn);
        k_dirichlet<<<grid, 256>>>(near_i, A, F, n, nt);
    }

    // Fluid interface penalty (must follow Dirichlet)
    {
        int threads = 128;
        int blocks  = (Ni + threads - 1) / threads;
        k_fluid_penalty<<<blocks, threads>>>(imap, A, Ni, nt);
    }
}